// round 12
// baseline (speedup 1.0000x reference)
#include <cuda_runtime.h>
#include <math.h>

#define B_SZ 4
#define N_PTS 8192
#define KNN 20
#define NCH 16
#define TILE 1024
#define THREADS 128
#define SPLIT 4                            // one split per warp
#define QPB 64                             // queries per block (2 per thread)
#define DQ 24                              // per-lane per-query buffer depth
#define NBLK ((B_SZ * N_PTS) / QPB)        // 512 knn blocks

__device__ float  g_dmax[B_SZ * N_PTS];
__device__ double g_p1[NBLK];
__device__ double g_p2[NBLK];
__device__ float  g_mv[2];

__device__ __forceinline__ void insert1(float (&r)[KNN], float v) {
#pragma unroll
    for (int k = KNN - 1; k >= 1; k--)
        r[k] = fminf(r[k], fmaxf(r[k - 1], v));
    r[0] = fminf(r[0], v);
}

__device__ __forceinline__ void drain_buf(float (&r)[KNN], const float* mybuf,
                                          int& cnt, float& r19) {
    const float INF = __int_as_float(0x7f800000);
    int jmax = (int)__reduce_max_sync(0xffffffffu, (unsigned)cnt);
    for (int j = 0; j < jmax; j++) {            // warp-uniform loop
        float v = mybuf[j * 32];                // lane-strided: conflict-free
        v = (j < cnt) ? v : INF;
        insert1(r, v);
    }
    cnt = 0;
    r19 = r[KNN - 1];
}

__global__ __launch_bounds__(THREADS, 4) void knn_kernel(const float* __restrict__ x) {
    __shared__ float4 sh[TILE];                           // 16 KB
    __shared__ float  buf[(THREADS / 32) * 2 * 32 * DQ];  // 24 KB; reused for merge

    const int warp = threadIdx.x >> 5, lane = threadIdx.x & 31;
    float* buf0 = buf + (warp * 2 + 0) * 32 * DQ + lane;  // query0 slots: [j*32]
    float* buf1 = buf + (warp * 2 + 1) * 32 * DQ + lane;  // query1 slots

    const int s = warp;                               // split 0..3

    const int blocks_per_batch = N_PTS / QPB;         // 128
    const int b = blockIdx.x / blocks_per_batch;
    const int n0 = (blockIdx.x % blocks_per_batch) * QPB + lane;       // query 0
    const int n1 = n0 + 32;                                            // query 1

    const float* xb = x + (size_t)b * 3 * N_PTS;
    const float qx0 = xb[n0], qy0 = xb[N_PTS + n0], qz0 = xb[2 * N_PTS + n0];
    const float qx1 = xb[n1], qy1 = xb[N_PTS + n1], qz1 = xb[2 * N_PTS + n1];
    const float qsq0 = fmaf(qx0, qx0, fmaf(qy0, qy0, qz0 * qz0));
    const float qsq1 = fmaf(qx1, qx1, fmaf(qy1, qy1, qz1 * qz1));

    // top-20 per query in e-space: e = |p|^2 - 2 q.p (order-preserving)
    const float INF = __int_as_float(0x7f800000);
    float r0[KNN], r1[KNN];
#pragma unroll
    for (int k = 0; k < KNN; k++) { r0[k] = INF; r1[k] = INF; }
    float r19_0 = INF, r19_1 = INF;
    int cnt0 = 0, cnt1 = 0;

    for (int t = 0; t < N_PTS; t += TILE) {
        __syncthreads();
        for (int i = threadIdx.x; i < TILE; i += THREADS) {
            float px = xb[t + i];
            float py = xb[N_PTS + t + i];
            float pz = xb[2 * N_PTS + t + i];
            float psq = fmaf(px, px, fmaf(py, py, pz * pz));
            sh[i] = make_float4(-2.f * px, -2.f * py, -2.f * pz, psq);
        }
        __syncthreads();

        const float4* shs = sh + s;        // split s scans i ≡ s (mod 4)
        int jstart = 0;
        if (t == 0) {
            // seed both queries: first 32 candidates inserted unconditionally
            for (int j = 0; j < 32; j++) {
                float4 p = shs[j << 2];
                insert1(r0, fmaf(qx0, p.x, fmaf(qy0, p.y, fmaf(qz0, p.z, p.w))));
                insert1(r1, fmaf(qx1, p.x, fmaf(qy1, p.y, fmaf(qz1, p.z, p.w))));
            }
            r19_0 = r0[KNN - 1];
            r19_1 = r1[KNN - 1];
            jstart = 32;
        }
        for (int j = jstart; j < TILE / SPLIT; j += 8) {
            if (__any_sync(0xffffffffu, (cnt0 >= DQ - 8) | (cnt1 >= DQ - 8))) {
                drain_buf(r0, buf0, cnt0, r19_0);
                drain_buf(r1, buf1, cnt1, r19_1);
            }
#pragma unroll
            for (int u = 0; u < 8; u++) {
                float4 p = shs[(j + u) << 2];   // one broadcast LDS, two queries
                float e0 = fmaf(qx0, p.x, fmaf(qy0, p.y, fmaf(qz0, p.z, p.w)));
                float e1 = fmaf(qx1, p.x, fmaf(qy1, p.y, fmaf(qz1, p.z, p.w)));
                bool a0 = e0 < r19_0;
                buf0[cnt0 * 32] = e0; cnt0 += (int)a0;
                bool a1 = e1 < r19_1;
                buf1[cnt1 * 32] = e1; cnt1 += (int)a1;
            }
        }
    }
    drain_buf(r0, buf0, cnt0, r19_0);     // tail drains
    drain_buf(r1, buf1, cnt1, r19_1);

    // ---- merge the 4 split lists per query (exact top-20 of union) ----
    __syncthreads();                       // buf now free -> merge storage
    // per (split,lane): 40 floats at stride 43 -> conflict-free reads
    float* mbuf = buf;
    if (s >= 1) {
        int base = ((s - 1) * 32 + lane) * 43;
#pragma unroll
        for (int k = 0; k < KNN; k++) {
            mbuf[base + k]       = r0[k];
            mbuf[base + KNN + k] = r1[k];
        }
    }
    __syncthreads();

    if (s == 0) {
        for (int m = 0; m < SPLIT - 1; m++) {
            int base = (m * 32 + lane) * 43;
#pragma unroll
            for (int k = 0; k < KNN; k++) {
                insert1(r0, mbuf[base + k]);
                insert1(r1, mbuf[base + KNN + k]);
            }
        }

        // finalize both queries: d2-space, clamp, sqrt, stats in double
        double s1 = 0.0, s2 = 0.0;
#pragma unroll
        for (int k = 0; k < KNN; k++) {
            float d2a = fmaxf(r0[k] + qsq0, 0.f);
            float d2b = fmaxf(r1[k] + qsq1, 0.f);
            s1 += (double)sqrtf(d2a) + (double)sqrtf(d2b);
            s2 += (double)d2a + (double)d2b;
        }
        g_dmax[b * N_PTS + n0] = sqrtf(fmaxf(r0[KNN - 1] + qsq0, 0.f));
        g_dmax[b * N_PTS + n1] = sqrtf(fmaxf(r1[KNN - 1] + qsq1, 0.f));

#pragma unroll
        for (int o = 16; o > 0; o >>= 1) {
            s1 += __shfl_xor_sync(0xffffffffu, s1, o);
            s2 += __shfl_xor_sync(0xffffffffu, s2, o);
        }
        if (lane == 0) {
            g_p1[blockIdx.x] = s1;
            g_p2[blockIdx.x] = s2;
        }
    }
}

__global__ void stats_kernel() {
    __shared__ double sr1[4], sr2[4];
    int t = threadIdx.x;
    double v1 = 0.0, v2 = 0.0;
#pragma unroll
    for (int i = 0; i < NBLK / 128; i++) {
        v1 += g_p1[t + i * 128];
        v2 += g_p2[t + i * 128];
    }
#pragma unroll
    for (int o = 16; o > 0; o >>= 1) {
        v1 += __shfl_xor_sync(0xffffffffu, v1, o);
        v2 += __shfl_xor_sync(0xffffffffu, v2, o);
    }
    if ((t & 31) == 0) { sr1[t >> 5] = v1; sr2[t >> 5] = v2; }
    __syncthreads();
    if (t == 0) {
        double s1 = sr1[0] + sr1[1] + sr1[2] + sr1[3];
        double s2 = sr2[0] + sr2[1] + sr2[2] + sr2[3];
        const double M = (double)(B_SZ * N_PTS * KNN);
        double m = s1 / M;
        double var = s2 / M - m * m;
        if (var < 0.0) var = 0.0;
        g_mv[0] = (float)m;
        g_mv[1] = (float)var;
    }
}

__global__ __launch_bounds__(256) void out_kernel(const float* __restrict__ conv_w,
                                                  const float* __restrict__ gamma,
                                                  const float* __restrict__ beta,
                                                  float* __restrict__ out) {
    __shared__ float s_s[NCH], s_t[NCH];
    if (threadIdx.x < NCH) {
        int c = threadIdx.x;
        float m = g_mv[0];
        float v = g_mv[1];
        float w = conv_w[c];
        float s = gamma[c] * w * rsqrtf(fmaf(w * w, v, 1e-5f));
        s_s[c] = s;
        s_t[c] = beta[c] - s * m;   // conv_b cancels in training-mode BN
    }
    __syncthreads();

    int q = blockIdx.x * blockDim.x + threadIdx.x;
    int b = q / N_PTS, n = q % N_PTS;
    float dmax = g_dmax[q];
#pragma unroll
    for (int c = 0; c < NCH; c++) {
        float s = s_s[c];
        float knn = (s >= 0.f) ? dmax : 0.f;  // min knn = 0 (self-distance)
        float y = fmaf(s, knn, s_t[c]);
        y = (y >= 0.f) ? y : 0.2f * y;        // LeakyReLU commutes with max_k
        out[((size_t)b * NCH + c) * N_PTS + n] = y;
    }
}

extern "C" void kernel_launch(void* const* d_in, const int* in_sizes, int n_in,
                              void* d_out, int out_size) {
    const float* x      = (const float*)d_in[0];
    const float* conv_w = (const float*)d_in[1];
    const float* gamma  = (const float*)d_in[3];
    const float* beta   = (const float*)d_in[4];
    float* out = (float*)d_out;

    knn_kernel<<<NBLK, THREADS>>>(x);
    stats_kernel<<<1, 128>>>();
    out_kernel<<<(B_SZ * N_PTS) / 256, 256>>>(conv_w, gamma, beta, out);
}

// round 13
// speedup vs baseline: 1.1824x; 1.1824x over previous
#include <cuda_runtime.h>
#include <math.h>

#define B_SZ 4
#define N_PTS 8192
#define KNN 20
#define NCH 16
#define TILE 1024
#define THREADS 128
#define SPLIT 4                            // one split per warp
#define QPB 32                             // queries per block (= lane)
#define DQ 24                              // per-lane buffer depth
#define NBLK ((B_SZ * N_PTS) / QPB)        // 1024 knn blocks

__device__ float  g_dmax[B_SZ * N_PTS];
__device__ double g_p1[NBLK];
__device__ double g_p2[NBLK];
__device__ float  g_mv[2];

__device__ __forceinline__ void insert1(float (&r)[KNN], float v) {
#pragma unroll
    for (int k = KNN - 1; k >= 1; k--)
        r[k] = fminf(r[k], fmaxf(r[k - 1], v));
    r[0] = fminf(r[0], v);
}

// drain + publish this split's 20th-best into the shared per-query threshold
__device__ __forceinline__ void drain_buf(float (&r)[KNN], const float* mybuf,
                                          int& cnt, float& r19,
                                          volatile float* tslot) {
    const float INF = __int_as_float(0x7f800000);
    int jmax = (int)__reduce_max_sync(0xffffffffu, (unsigned)cnt);
    for (int j = 0; j < jmax; j++) {            // warp-uniform loop
        float v = mybuf[j * 32];                // lane-strided: conflict-free
        v = (j < cnt) ? v : INF;
        insert1(r, v);
    }
    cnt = 0;
    // racy monotone min across the 4 splits: always a valid upper bound of
    // the union's 20th-best -> conservative admission threshold
    float t = fminf(*tslot, r[KNN - 1]);
    *tslot = t;
    r19 = t;
}

__global__ __launch_bounds__(THREADS, 7) void knn_kernel(const float* __restrict__ x) {
    __shared__ float4 sh[TILE];                       // 16 KB
    __shared__ float  buf[(THREADS / 32) * 32 * DQ];  // 12 KB; reused for merge
    __shared__ float  thr[QPB];                       // shared per-query threshold

    const int warp = threadIdx.x >> 5, lane = threadIdx.x & 31;
    float* mybuf = buf + warp * 32 * DQ + lane;       // slot j -> mybuf[j*32]
    volatile float* thrv = thr;

    const int ql = lane;                              // local query 0..31
    const int s  = warp;                              // split 0..3

    const int blocks_per_batch = N_PTS / QPB;         // 256
    const int b = blockIdx.x / blocks_per_batch;
    const int n = (blockIdx.x % blocks_per_batch) * QPB + ql;

    const float* xb = x + (size_t)b * 3 * N_PTS;
    const float qx = xb[n];
    const float qy = xb[N_PTS + n];
    const float qz = xb[2 * N_PTS + n];
    const float qsq = fmaf(qx, qx, fmaf(qy, qy, qz * qz));

    // top-20 in e-space: e = |p|^2 - 2 q.p = d2 - qsq (order-preserving)
    const float INF = __int_as_float(0x7f800000);
    float r[KNN];
#pragma unroll
    for (int k = 0; k < KNN; k++) r[k] = INF;
    float r19 = INF;
    int cnt = 0;

    if (threadIdx.x < QPB) thr[threadIdx.x] = INF;    // covered by first barrier

    for (int t = 0; t < N_PTS; t += TILE) {
        __syncthreads();
        for (int i = threadIdx.x; i < TILE; i += THREADS) {
            float px = xb[t + i];
            float py = xb[N_PTS + t + i];
            float pz = xb[2 * N_PTS + t + i];
            float psq = fmaf(px, px, fmaf(py, py, pz * pz));
            sh[i] = make_float4(-2.f * px, -2.f * py, -2.f * pz, psq);
        }
        __syncthreads();

        const float4* shs = sh + s;        // split s scans i ≡ s (mod 4)
        int jstart = 0;
        if (t == 0) {
            // seed: first 32 candidates inserted unconditionally -> real r19,
            // then publish to the shared threshold
            for (int j = 0; j < 32; j++) {
                float4 p = shs[j << 2];
                float e = fmaf(qx, p.x, fmaf(qy, p.y, fmaf(qz, p.z, p.w)));
                insert1(r, e);
            }
            float tt = fminf(thrv[lane], r[KNN - 1]);
            thrv[lane] = tt;
            r19 = tt;
            jstart = 32;
        }
        for (int j = jstart; j < TILE / SPLIT; j += 16) {
            if (__any_sync(0xffffffffu, cnt >= DQ - 16))
                drain_buf(r, mybuf, cnt, r19, thrv + lane);
            // refresh vs the cross-split shared threshold (fresher than r19)
            float tg = fminf(r19, thrv[lane]);
#pragma unroll
            for (int u = 0; u < 16; u++) {
                float4 p = shs[(j + u) << 2];   // warp-uniform -> broadcast
                float e = fmaf(qx, p.x, fmaf(qy, p.y, fmaf(qz, p.z, p.w)));
                bool q = e < tg;
                mybuf[cnt * 32] = e;      // unconditional; commits only if q
                cnt += (int)q;
            }
        }
    }
    drain_buf(r, mybuf, cnt, r19, thrv + lane);   // tail drain

    // ---- merge the 4 split lists per query (exact top-20 of union) ----
    __syncthreads();                       // buf now free -> merge storage
    float* mbuf = buf;                     // [(s-1)*32 + ql]*21 + k (pad 21)
    if (s >= 1) {
#pragma unroll
        for (int k = 0; k < KNN; k++)
            mbuf[((s - 1) * QPB + ql) * 21 + k] = r[k];
    }
    __syncthreads();

    if (s == 0) {
        for (int m = 0; m < SPLIT - 1; m++)
#pragma unroll
            for (int k = 0; k < KNN; k++)
                insert1(r, mbuf[(m * QPB + ql) * 21 + k]);

        // finalize: back to d2-space, clamp, sqrt, stats in double
        double s1 = 0.0, s2 = 0.0;
#pragma unroll
        for (int k = 0; k < KNN; k++) {
            float d2 = fmaxf(r[k] + qsq, 0.f);
            float d = sqrtf(d2);
            s1 += (double)d;
            s2 += (double)d2;
        }
        g_dmax[b * N_PTS + n] = sqrtf(fmaxf(r[KNN - 1] + qsq, 0.f));

#pragma unroll
        for (int o = 16; o > 0; o >>= 1) {
            s1 += __shfl_xor_sync(0xffffffffu, s1, o);
            s2 += __shfl_xor_sync(0xffffffffu, s2, o);
        }
        if (lane == 0) {
            g_p1[blockIdx.x] = s1;
            g_p2[blockIdx.x] = s2;
        }
    }
}

__global__ void stats_kernel() {
    __shared__ double sr1[4], sr2[4];
    int t = threadIdx.x;
    double v1 = 0.0, v2 = 0.0;
#pragma unroll
    for (int i = 0; i < NBLK / 128; i++) {
        v1 += g_p1[t + i * 128];
        v2 += g_p2[t + i * 128];
    }
#pragma unroll
    for (int o = 16; o > 0; o >>= 1) {
        v1 += __shfl_xor_sync(0xffffffffu, v1, o);
        v2 += __shfl_xor_sync(0xffffffffu, v2, o);
    }
    if ((t & 31) == 0) { sr1[t >> 5] = v1; sr2[t >> 5] = v2; }
    __syncthreads();
    if (t == 0) {
        double s1 = sr1[0] + sr1[1] + sr1[2] + sr1[3];
        double s2 = sr2[0] + sr2[1] + sr2[2] + sr2[3];
        const double M = (double)(B_SZ * N_PTS * KNN);
        double m = s1 / M;
        double var = s2 / M - m * m;
        if (var < 0.0) var = 0.0;
        g_mv[0] = (float)m;
        g_mv[1] = (float)var;
    }
}

__global__ __launch_bounds__(256) void out_kernel(const float* __restrict__ conv_w,
                                                  const float* __restrict__ gamma,
                                                  const float* __restrict__ beta,
                                                  float* __restrict__ out) {
    __shared__ float s_s[NCH], s_t[NCH];
    if (threadIdx.x < NCH) {
        int c = threadIdx.x;
        float m = g_mv[0];
        float v = g_mv[1];
        float w = conv_w[c];
        float s = gamma[c] * w * rsqrtf(fmaf(w * w, v, 1e-5f));
        s_s[c] = s;
        s_t[c] = beta[c] - s * m;   // conv_b cancels in training-mode BN
    }
    __syncthreads();

    int q = blockIdx.x * blockDim.x + threadIdx.x;
    int b = q / N_PTS, n = q % N_PTS;
    float dmax = g_dmax[q];
#pragma unroll
    for (int c = 0; c < NCH; c++) {
        float s = s_s[c];
        float knn = (s >= 0.f) ? dmax : 0.f;  // min knn = 0 (self-distance)
        float y = fmaf(s, knn, s_t[c]);
        y = (y >= 0.f) ? y : 0.2f * y;        // LeakyReLU commutes with max_k
        out[((size_t)b * NCH + c) * N_PTS + n] = y;
    }
}

extern "C" void kernel_launch(void* const* d_in, const int* in_sizes, int n_in,
                              void* d_out, int out_size) {
    const float* x      = (const float*)d_in[0];
    const float* conv_w = (const float*)d_in[1];
    const float* gamma  = (const float*)d_in[3];
    const float* beta   = (const float*)d_in[4];
    float* out = (float*)d_out;

    knn_kernel<<<NBLK, THREADS>>>(x);
    stats_kernel<<<1, 128>>>();
    out_kernel<<<(B_SZ * N_PTS) / 256, 256>>>(conv_w, gamma, beta, out);
}